// round 13
// baseline (speedup 1.0000x reference)
#include <cuda_runtime.h>
#include <cstdint>
#include <cstddef>

typedef unsigned long long ull;

#define KD    9
#define PADV  4
#define BATCH 2
#define CCH   64
#define HH    32
#define WW    32
#define DD    32
#define TW    8
#define NTHR  288          // 9 dx * 8 wl * 4 dbk -> 9 warps, all active

#define CCHUNK 8
#define NCHUNK (CCH / CCHUNK)   // 8

// smem (floats):
//   in1 tile: [c][w][d]     stride 36 (32 data + 4 pad), all 64 ch resident, LDS.128 conflict-free
//   in2 halo: [cc][row][d'] stride 44 (4 zero | 32 data | 4 zero | 4 pad), 8-ch chunk, 16 rows
#define IN1_STRIDE 36
#define IN1_FLOATS (CCH*TW*IN1_STRIDE)              // 18432  (73728 B)
#define IN2_ROWS   16
#define IN2_STRIDE 44
#define IN2_FLOATS (CCHUNK*IN2_ROWS*IN2_STRIDE)     // 5632   (22528 B)
#define SMEM_BYTES ((IN1_FLOATS + IN2_FLOATS)*4)    // 96256 B -> 2 CTAs/SM

__device__ __forceinline__ ull pack2f(float lo, float hi) {
    ull r;
    asm("mov.b64 %0, {%1, %2};" : "=l"(r) : "f"(lo), "f"(hi));
    return r;
}
// packed f32x2 FMA: d = a*b + d  (FFMA2; only reachable via PTX)
__device__ __forceinline__ void ffma2(ull& d, ull a, ull b) {
    asm("fma.rn.f32x2 %0, %1, %2, %0;" : "+l"(d) : "l"(a), "l"(b));
}

__global__ void __launch_bounds__(NTHR, 2)
corr3d_kernel(const float* __restrict__ in1, const float* __restrict__ in2,
              float* __restrict__ out)
{
    extern __shared__ float sm[];
    float* s1 = sm;               // in1 tile (all 64 channels)
    float* s2 = sm + IN1_FLOATS;  // in2 halo rows (one 8-channel chunk)

    const int tid = threadIdx.x;
    const int w0  = blockIdx.x * TW;
    const int h   = blockIdx.y;
    const int b   = blockIdx.z & 1;        // z = dy*2 + b
    const int dy  = blockIdx.z >> 1;

    // thread mapping: tid = dx*32 + wl*4 + dbk  (warp == dx)
    const int dx  = tid >> 5;        // 0..8
    const int wl  = (tid >> 2) & 7;  // 0..7
    const int dbk = tid & 3;         // 0..3
    const int d0  = dbk << 3;        // 0,8,16,24
    const int row = wl + dx;         // in2 halo row index 0..15

    ull acc[KD][4];
    #pragma unroll
    for (int z = 0; z < KD; ++z) {
        #pragma unroll
        for (int j = 0; j < 4; ++j) acc[z][j] = 0ULL;
    }

    const int hp = h + dy - PADV;    // uniform across block
    if ((unsigned)hp < (unsigned)HH) {
        // Zero in2 buffer: d-edge pads and OOB-w rows stay zero across restages
        // (every restage rewrites exactly the same valid-cell pattern).
        for (int i = tid; i < IN2_FLOATS; i += NTHR) s2[i] = 0.0f;

        // Stage full in1 tile: 64c x 8w x 8 float4
        #pragma unroll 1
        for (int i = tid; i < CCH*TW*8; i += NTHR) {
            int j  = i & 7;
            int rw = i >> 3;
            int c  = rw >> 3;
            int w  = rw & 7;
            const float4 v = *reinterpret_cast<const float4*>(
                in1 + ((((size_t)b*CCH + c)*HH + h)*WW + (w0 + w))*DD + j*4);
            *reinterpret_cast<float4*>(s1 + (c*TW + w)*IN1_STRIDE + j*4) = v;
        }

        const float* in2b = in2 + ((size_t)b*CCH)*HH*WW*DD;

        for (int ck = 0; ck < NCHUNK; ++ck) {
            const int c0 = ck * CCHUNK;
            __syncthreads();   // prev compute (or init/in1-stage) done before restage

            // Stage 8 channels x 16 in2 rows at h'=hp  (1024 float4)
            #pragma unroll 1
            for (int i = tid; i < CCHUNK*IN2_ROWS*8; i += NTHR) {
                int j  = i & 7;
                int rr = i >> 3;
                int cl = rr >> 4;          // 0..7
                int r  = rr & 15;          // 0..15
                int wp = w0 + r - PADV;
                if ((unsigned)wp < (unsigned)WW) {
                    const float4 v = *reinterpret_cast<const float4*>(
                        in2b + ((size_t)(c0 + cl))*(HH*WW*DD) + (hp*WW + wp)*DD + j*4);
                    *reinterpret_cast<float4*>(
                        s2 + (cl*IN2_ROWS + r)*IN2_STRIDE + 4 + j*4) = v;
                }
            }
            __syncthreads();

            const ull* p1 = reinterpret_cast<const ull*>(s1)
                            + (c0*TW + wl)*(IN1_STRIDE/2) + (d0 >> 1);
            const ull* p2 = reinterpret_cast<const ull*>(s2)
                            + row*(IN2_STRIDE/2) + (d0 >> 1);
            #pragma unroll 1
            for (int c = 0; c < CCHUNK; ++c) {
                // V[0..7]: in2 floats [d0 .. d0+15]; A[0..3]: in1 floats [d0..d0+7]
                ull V[8], A[4];
                {
                    ulonglong2 t0 = *reinterpret_cast<const ulonglong2*>(p2);
                    ulonglong2 t1 = *reinterpret_cast<const ulonglong2*>(p2 + 2);
                    ulonglong2 t2 = *reinterpret_cast<const ulonglong2*>(p2 + 4);
                    ulonglong2 t3 = *reinterpret_cast<const ulonglong2*>(p2 + 6);
                    V[0]=t0.x; V[1]=t0.y; V[2]=t1.x; V[3]=t1.y;
                    V[4]=t2.x; V[5]=t2.y; V[6]=t3.x; V[7]=t3.y;
                    ulonglong2 a0 = *reinterpret_cast<const ulonglong2*>(p1);
                    ulonglong2 a1 = *reinterpret_cast<const ulonglong2*>(p1 + 2);
                    A[0]=a0.x; A[1]=a0.y; A[2]=a1.x; A[3]=a1.y;
                }
                #pragma unroll
                for (int j = 0; j < 4; ++j) {
                    // even dz: aligned pairs straight from V
                    #pragma unroll
                    for (int dz = 0; dz < KD; dz += 2)
                        ffma2(acc[dz][j], V[j + (dz >> 1)], A[j]);
                    // odd dz: odd-aligned pair built on the fly
                    #pragma unroll
                    for (int dz = 1; dz < KD; dz += 2) {
                        int m = j + ((dz - 1) >> 1);
                        ull ov = pack2f(
                            __uint_as_float((unsigned)(V[m]   >> 32)),
                            __uint_as_float((unsigned)(V[m+1] & 0xFFFFFFFFu)));
                        ffma2(acc[dz][j], ov, A[j]);
                    }
                }
                p1 += TW * (IN1_STRIDE/2);        // 144 ull per channel
                p2 += IN2_ROWS * (IN2_STRIDE/2);  // 352 ull per channel
            }
        }
    }

    // write (zeros if hp was out of range — output buffer is poisoned)
    {
        const int kbase = (dy*KD + dx)*KD;
        float* op = out + (((size_t)b*(KD*KD*KD) + kbase)*HH + h)*(WW*DD)
                        + (w0 + wl)*DD + d0;
        #pragma unroll
        for (int dz = 0; dz < KD; ++dz) {
            ulonglong2 v0; v0.x = acc[dz][0]; v0.y = acc[dz][1];
            ulonglong2 v1; v1.x = acc[dz][2]; v1.y = acc[dz][3];
            *reinterpret_cast<ulonglong2*>(op)     = v0;   // 16B stores, aligned
            *reinterpret_cast<ulonglong2*>(op + 4) = v1;
            op += (size_t)HH * WW * DD;                    // next dz channel
        }
    }
}

extern "C" void kernel_launch(void* const* d_in, const int* in_sizes, int n_in,
                              void* d_out, int out_size)
{
    const float* in1 = (const float*)d_in[0];
    const float* in2 = (const float*)d_in[1];
    float* out = (float*)d_out;

    cudaFuncSetAttribute(corr3d_kernel,
                         cudaFuncAttributeMaxDynamicSharedMemorySize, SMEM_BYTES);

    dim3 grid(WW / TW, HH, BATCH * KD);   // 4 x 32 x 18 = 2304 blocks, z = dy*2 + b
    corr3d_kernel<<<grid, NTHR, SMEM_BYTES>>>(in1, in2, out);
}

// round 14
// speedup vs baseline: 1.5228x; 1.5228x over previous
#include <cuda_runtime.h>
#include <cstdint>
#include <cstddef>

typedef unsigned long long ull;

#define KD    9
#define PADV  4
#define BATCH 2
#define CCH   64
#define HH    32
#define WW    32
#define DD    32
#define TW    4
#define NTHR  288          // 9 dx * 4 wl * 8 dbk -> 9 warps, all active

#define CCHUNK 8
#define NCHUNK (CCH / CCHUNK)   // 8

// smem (floats):
//   in1 tile: [c][w][d]     stride 36 (32 data + 4 pad), all 64 ch resident, LDS.128-aligned
//   in2 halo: 2 buffers of [cc][row][d'] stride 44 (4 zero | 32 | 4 zero | 4 pad), 8-ch chunk
#define IN1_STRIDE 36
#define IN1_FLOATS (CCH*TW*IN1_STRIDE)              // 9216   (36864 B)
#define IN2_ROWS   12
#define IN2_STRIDE 44
#define IN2_BUF    (CCHUNK*IN2_ROWS*IN2_STRIDE)     // 4224   (16896 B)
#define IN2_FLOATS (2*IN2_BUF)                      // 8448
#define SMEM_BYTES ((IN1_FLOATS + IN2_FLOATS)*4)    // 70656 B -> 3 CTAs/SM

#define STAGE_V4 (CCHUNK*IN2_ROWS*8)                // 768 float4 per chunk
#define NLD 3                                       // ceil(768/288)

__device__ __forceinline__ ull pack2f(float lo, float hi) {
    ull r;
    asm("mov.b64 %0, {%1, %2};" : "=l"(r) : "f"(lo), "f"(hi));
    return r;
}
// packed f32x2 FMA: d = a*b + d  (FFMA2; only reachable via PTX)
__device__ __forceinline__ void ffma2(ull& d, ull a, ull b) {
    asm("fma.rn.f32x2 %0, %1, %2, %0;" : "+l"(d) : "l"(a), "l"(b));
}
__device__ __forceinline__ unsigned su32(const void* p) {
    return (unsigned)__cvta_generic_to_shared(p);
}
#define CP16(s, g)   asm volatile("cp.async.cg.shared.global [%0], [%1], 16;" :: "r"(s), "l"(g))
#define CP_COMMIT()  asm volatile("cp.async.commit_group;")
#define CP_WAIT0()   asm volatile("cp.async.wait_group 0;")

__global__ void __launch_bounds__(NTHR, 3)
corr3d_kernel(const float* __restrict__ in1, const float* __restrict__ in2,
              float* __restrict__ out)
{
    extern __shared__ float sm[];
    float* s1 = sm;               // in1 tile (all 64 channels)
    float* s2 = sm + IN1_FLOATS;  // in2 halo: two 8-channel buffers

    const int tid = threadIdx.x;
    const int w0  = blockIdx.x * TW;
    const int h   = blockIdx.y;
    const int b   = blockIdx.z & 1;        // z = dy*2 + b
    const int dy  = blockIdx.z >> 1;

    // thread mapping: tid = dx*32 + wl*8 + dbk  (warp == dx)
    const int dx  = tid >> 5;        // 0..8
    const int wl  = (tid >> 3) & 3;  // 0..3
    const int dbk = tid & 7;         // 0..7
    const int d0  = dbk << 2;        // 0,4,...,28
    const int row = wl + dx;         // in2 halo row index 0..11

    ull acc[KD][2];
    #pragma unroll
    for (int z = 0; z < KD; ++z) { acc[z][0] = 0ULL; acc[z][1] = 0ULL; }

    const int hp = h + dy - PADV;    // uniform across block
    if ((unsigned)hp < (unsigned)HH) {
        // Zero both in2 buffers: d-edge pads and OOB-w rows stay zero across
        // restages (every chunk rewrites exactly the same valid-cell pattern).
        for (int i = tid; i < IN2_FLOATS; i += NTHR) s2[i] = 0.0f;

        // Stage full in1 tile: 64c x 4w x 8 float4
        #pragma unroll 1
        for (int i = tid; i < CCH*TW*8; i += NTHR) {
            int j  = i & 7;
            int rw = i >> 3;
            int c  = rw >> 2;
            int w  = rw & 3;
            const float4 v = *reinterpret_cast<const float4*>(
                in1 + ((((size_t)b*CCH + c)*HH + h)*WW + (w0 + w))*DD + j*4);
            *reinterpret_cast<float4*>(s1 + (c*TW + w)*IN1_STRIDE + j*4) = v;
        }

        // per-thread staging geometry (chunk-invariant)
        const float* gdy = in2 + ((size_t)b*CCH)*HH*WW*DD + (size_t)hp*(WW*DD);
        unsigned st_sm[NLD];   // smem byte-offset within a buffer
        int      st_g[NLD];    // gmem float-offset from gdy (chunk channel 0)
        bool     st_ok[NLD];
        #pragma unroll
        for (int k = 0; k < NLD; ++k) {
            int i = tid + k*NTHR;
            if (i < STAGE_V4) {
                int j  = i & 7;
                int rr = i >> 3;            // 0..95
                int cl = rr / IN2_ROWS;     // 0..7
                int r  = rr - cl*IN2_ROWS;  // 0..11
                int wp = w0 + r - PADV;
                st_ok[k] = ((unsigned)wp < (unsigned)WW);
                st_sm[k] = (unsigned)(((cl*IN2_ROWS + r)*IN2_STRIDE + 4 + j*4) * 4);
                st_g[k]  = cl*(HH*WW*DD) + wp*DD + j*4;
            } else { st_ok[k] = false; st_sm[k] = 0; st_g[k] = 0; }
        }

        __syncthreads();   // zero-init + in1 visible before first cp.async lands

        const unsigned sbase = su32(s2);

        // prologue: issue chunk 0 into buffer 0
        #pragma unroll
        for (int k = 0; k < NLD; ++k)
            if (st_ok[k]) CP16(sbase + st_sm[k], gdy + st_g[k]);
        CP_COMMIT();

        for (int ck = 0; ck < NCHUNK; ++ck) {
            CP_WAIT0();        // chunk ck landed (sole pending group)
            __syncthreads();   // data visible to all warps; compute(ck-1) finished

            // issue chunk ck+1 into the other buffer (last read by compute(ck-1))
            if (ck + 1 < NCHUNK) {
                const unsigned sb = sbase + (unsigned)(((ck + 1) & 1) * IN2_BUF * 4);
                const float* g = gdy + (size_t)((ck + 1)*CCHUNK)*(HH*WW*DD);
                #pragma unroll
                for (int k = 0; k < NLD; ++k)
                    if (st_ok[k]) CP16(sb + st_sm[k], g + st_g[k]);
                CP_COMMIT();
            }

            // compute chunk ck
            const ull* p1 = reinterpret_cast<const ull*>(s1)
                            + ((ck*CCHUNK)*TW + wl)*(IN1_STRIDE/2) + (d0 >> 1);
            const ull* p2 = reinterpret_cast<const ull*>(s2 + (ck & 1)*IN2_BUF)
                            + row*(IN2_STRIDE/2) + (d0 >> 1);
            #pragma unroll 1
            for (int c = 0; c < CCHUNK; ++c) {
                // V[0..5]: in2 floats [d0 .. d0+11]; A: in1 floats [d0..d0+3]
                ull V[6], A[2];
                {
                    ulonglong2 t0 = *reinterpret_cast<const ulonglong2*>(p2);
                    ulonglong2 t1 = *reinterpret_cast<const ulonglong2*>(p2 + 2);
                    ulonglong2 t2 = *reinterpret_cast<const ulonglong2*>(p2 + 4);
                    V[0]=t0.x; V[1]=t0.y; V[2]=t1.x; V[3]=t1.y; V[4]=t2.x; V[5]=t2.y;
                    ulonglong2 ta = *reinterpret_cast<const ulonglong2*>(p1);
                    A[0]=ta.x; A[1]=ta.y;
                }
                #pragma unroll
                for (int j = 0; j < 2; ++j) {
                    // even dz: aligned pairs straight from V
                    #pragma unroll
                    for (int dz = 0; dz < KD; dz += 2)
                        ffma2(acc[dz][j], V[j + (dz >> 1)], A[j]);
                    // odd dz: odd-aligned pair built on the fly
                    #pragma unroll
                    for (int dz = 1; dz < KD; dz += 2) {
                        int m = j + ((dz - 1) >> 1);
                        ull ov = pack2f(
                            __uint_as_float((unsigned)(V[m]   >> 32)),
                            __uint_as_float((unsigned)(V[m+1] & 0xFFFFFFFFu)));
                        ffma2(acc[dz][j], ov, A[j]);
                    }
                }
                p1 += TW * (IN1_STRIDE/2);        // 72 ull per channel
                p2 += IN2_ROWS * (IN2_STRIDE/2);  // 264 ull per channel
            }
        }
    }

    // write (zeros if hp was out of range — output buffer is poisoned)
    {
        const int kbase = (dy*KD + dx)*KD;
        float* op = out + (((size_t)b*(KD*KD*KD) + kbase)*HH + h)*(WW*DD)
                        + (w0 + wl)*DD + d0;
        #pragma unroll
        for (int dz = 0; dz < KD; ++dz) {
            ulonglong2 v0; v0.x = acc[dz][0]; v0.y = acc[dz][1];
            *reinterpret_cast<ulonglong2*>(op) = v0;     // 16B store, aligned
            op += (size_t)HH * WW * DD;                  // next dz channel
        }
    }
}

extern "C" void kernel_launch(void* const* d_in, const int* in_sizes, int n_in,
                              void* d_out, int out_size)
{
    const float* in1 = (const float*)d_in[0];
    const float* in2 = (const float*)d_in[1];
    float* out = (float*)d_out;

    cudaFuncSetAttribute(corr3d_kernel,
                         cudaFuncAttributeMaxDynamicSharedMemorySize, SMEM_BYTES);

    dim3 grid(WW / TW, HH, BATCH * KD);   // 8 x 32 x 18 = 4608 blocks, z = dy*2 + b
    corr3d_kernel<<<grid, NTHR, SMEM_BYTES>>>(in1, in2, out);
}

// round 15
// speedup vs baseline: 1.5694x; 1.0306x over previous
#include <cuda_runtime.h>
#include <cstdint>
#include <cstddef>

typedef unsigned long long ull;

#define KD    9
#define PADV  4
#define BATCH 2
#define CCH   64
#define HH    32
#define WW    32
#define DD    32
#define TW    4
#define NTHR  288          // 9 dx * 4 wl * 8 dbk -> 9 warps, all active

#define CCHUNK 8
#define NCHUNK (CCH / CCHUNK)   // 8

// smem (floats):
//   in1 tile: [c][w][d]     stride 36 (32 data + 4 pad), all 64 ch resident, LDS.128-aligned
//   in2 halo: 2 buffers of [cc][row][d'] stride 40 (4 zero | 32 | 4 zero), 8-ch chunk
#define IN1_STRIDE 36
#define IN1_FLOATS (CCH*TW*IN1_STRIDE)              // 9216   (36864 B)
#define IN2_ROWS   12
#define IN2_STRIDE 40
#define IN2_BUF    (CCHUNK*IN2_ROWS*IN2_STRIDE)     // 3840   (15360 B)
#define IN2_FLOATS (2*IN2_BUF)                      // 7680
#define SMEM_BYTES ((IN1_FLOATS + IN2_FLOATS)*4)    // 67584 B -> 3 CTAs/SM

#define STAGE_V4 (CCHUNK*IN2_ROWS*8)                // 768 float4 per chunk
#define NLD 3                                       // ceil(768/288)

__device__ __forceinline__ ull pack2f(float lo, float hi) {
    ull r;
    asm("mov.b64 %0, {%1, %2};" : "=l"(r) : "f"(lo), "f"(hi));
    return r;
}
// packed f32x2 FMA: d = a*b + d  (FFMA2; only reachable via PTX)
__device__ __forceinline__ void ffma2(ull& d, ull a, ull b) {
    asm("fma.rn.f32x2 %0, %1, %2, %0;" : "+l"(d) : "l"(a), "l"(b));
}
__device__ __forceinline__ unsigned su32(const void* p) {
    return (unsigned)__cvta_generic_to_shared(p);
}
#define CP16(s, g)   asm volatile("cp.async.cg.shared.global [%0], [%1], 16;" :: "r"(s), "l"(g))
#define CP_COMMIT()  asm volatile("cp.async.commit_group;")
#define CP_WAIT0()   asm volatile("cp.async.wait_group 0;")

__global__ void __launch_bounds__(NTHR, 3)
corr3d_kernel(const float* __restrict__ in1, const float* __restrict__ in2,
              float* __restrict__ out)
{
    extern __shared__ float sm[];
    float* s1 = sm;               // in1 tile (all 64 channels)
    float* s2 = sm + IN1_FLOATS;  // in2 halo: two 8-channel buffers

    const int tid = threadIdx.x;
    const int w0  = blockIdx.x * TW;
    const int h   = blockIdx.y;
    const int b   = blockIdx.z & 1;        // z = dy*2 + b
    const int dy  = blockIdx.z >> 1;

    // thread mapping: tid = dx*32 + wl*8 + dbk  (warp == dx)
    const int dx  = tid >> 5;        // 0..8
    const int wl  = (tid >> 3) & 3;  // 0..3
    const int dbk = tid & 7;         // 0..7
    const int d0  = dbk << 2;        // 0,4,...,28
    const int row = wl + dx;         // in2 halo row index 0..11

    ull acc[KD][2];
    #pragma unroll
    for (int z = 0; z < KD; ++z) { acc[z][0] = 0ULL; acc[z][1] = 0ULL; }

    const int hp = h + dy - PADV;    // uniform across block
    if ((unsigned)hp < (unsigned)HH) {
        // Zero both in2 buffers: d-edge pads and OOB-w rows stay zero across
        // restages (every chunk rewrites exactly the same valid-cell pattern).
        for (int i = tid; i < IN2_FLOATS; i += NTHR) s2[i] = 0.0f;

        // per-thread in2 staging geometry (chunk-invariant)
        const float* gdy = in2 + ((size_t)b*CCH)*HH*WW*DD + (size_t)hp*(WW*DD);
        unsigned st_sm[NLD];   // smem byte-offset within a buffer
        int      st_g[NLD];    // gmem float-offset from gdy (chunk channel 0)
        bool     st_ok[NLD];
        #pragma unroll
        for (int k = 0; k < NLD; ++k) {
            int i = tid + k*NTHR;
            if (i < STAGE_V4) {
                int j  = i & 7;
                int rr = i >> 3;            // 0..95
                int cl = rr / IN2_ROWS;     // 0..7
                int r  = rr - cl*IN2_ROWS;  // 0..11
                int wp = w0 + r - PADV;
                st_ok[k] = ((unsigned)wp < (unsigned)WW);
                st_sm[k] = (unsigned)(((cl*IN2_ROWS + r)*IN2_STRIDE + 4 + j*4) * 4);
                st_g[k]  = cl*(HH*WW*DD) + wp*DD + j*4;
            } else { st_ok[k] = false; st_sm[k] = 0; st_g[k] = 0; }
        }

        __syncthreads();   // zero-init drained before async copies land

        const unsigned sbase  = su32(s2);
        const unsigned s1base = su32(s1);

        // prologue group: full in1 tile + in2 chunk 0  (one commit)
        {
            const float* g1 = in1 + (((size_t)b*CCH)*HH + h)*(WW*DD);
            #pragma unroll 1
            for (int i = tid; i < CCH*TW*8; i += NTHR) {
                int j  = i & 7;
                int rw = i >> 3;
                int c  = rw >> 2;
                int w  = rw & 3;
                CP16(s1base + (unsigned)(((c*TW + w)*IN1_STRIDE + j*4)*4),
                     g1 + (size_t)c*(HH*WW*DD) + (w0 + w)*DD + j*4);
            }
            #pragma unroll
            for (int k = 0; k < NLD; ++k)
                if (st_ok[k]) CP16(sbase + st_sm[k], gdy + st_g[k]);
            CP_COMMIT();
        }

        for (int ck = 0; ck < NCHUNK; ++ck) {
            CP_WAIT0();        // chunk ck (and, at ck=0, the in1 tile) landed
            __syncthreads();   // data visible to all warps; compute(ck-1) finished

            // issue chunk ck+1 into the other buffer (last read by compute(ck-1))
            if (ck + 1 < NCHUNK) {
                const unsigned sb = sbase + (unsigned)(((ck + 1) & 1) * IN2_BUF * 4);
                const float* g = gdy + (size_t)((ck + 1)*CCHUNK)*(HH*WW*DD);
                #pragma unroll
                for (int k = 0; k < NLD; ++k)
                    if (st_ok[k]) CP16(sb + st_sm[k], g + st_g[k]);
                CP_COMMIT();
            }

            // compute chunk ck
            const ull* p1 = reinterpret_cast<const ull*>(s1)
                            + ((ck*CCHUNK)*TW + wl)*(IN1_STRIDE/2) + (d0 >> 1);
            const ull* p2 = reinterpret_cast<const ull*>(s2 + (ck & 1)*IN2_BUF)
                            + row*(IN2_STRIDE/2) + (d0 >> 1);
            #pragma unroll 1
            for (int c = 0; c < CCHUNK; ++c) {
                // V[0..5]: in2 floats [d0 .. d0+11]; A: in1 floats [d0..d0+3]
                ull V[6], A[2];
                {
                    ulonglong2 t0 = *reinterpret_cast<const ulonglong2*>(p2);
                    ulonglong2 t1 = *reinterpret_cast<const ulonglong2*>(p2 + 2);
                    ulonglong2 t2 = *reinterpret_cast<const ulonglong2*>(p2 + 4);
                    V[0]=t0.x; V[1]=t0.y; V[2]=t1.x; V[3]=t1.y; V[4]=t2.x; V[5]=t2.y;
                    ulonglong2 ta = *reinterpret_cast<const ulonglong2*>(p1);
                    A[0]=ta.x; A[1]=ta.y;
                }
                #pragma unroll
                for (int j = 0; j < 2; ++j) {
                    // even dz: aligned pairs straight from V
                    #pragma unroll
                    for (int dz = 0; dz < KD; dz += 2)
                        ffma2(acc[dz][j], V[j + (dz >> 1)], A[j]);
                    // odd dz: odd-aligned pair built on the fly
                    #pragma unroll
                    for (int dz = 1; dz < KD; dz += 2) {
                        int m = j + ((dz - 1) >> 1);
                        ull ov = pack2f(
                            __uint_as_float((unsigned)(V[m]   >> 32)),
                            __uint_as_float((unsigned)(V[m+1] & 0xFFFFFFFFu)));
                        ffma2(acc[dz][j], ov, A[j]);
                    }
                }
                p1 += TW * (IN1_STRIDE/2);        // 72 ull per channel
                p2 += IN2_ROWS * (IN2_STRIDE/2);  // 240 ull per channel
            }
        }
    }

    // write (zeros if hp was out of range — output buffer is poisoned)
    {
        const int kbase = (dy*KD + dx)*KD;
        float* op = out + (((size_t)b*(KD*KD*KD) + kbase)*HH + h)*(WW*DD)
                        + (w0 + wl)*DD + d0;
        #pragma unroll
        for (int dz = 0; dz < KD; ++dz) {
            ulonglong2 v0; v0.x = acc[dz][0]; v0.y = acc[dz][1];
            *reinterpret_cast<ulonglong2*>(op) = v0;     // 16B store, aligned
            op += (size_t)HH * WW * DD;                  // next dz channel
        }
    }
}

extern "C" void kernel_launch(void* const* d_in, const int* in_sizes, int n_in,
                              void* d_out, int out_size)
{
    const float* in1 = (const float*)d_in[0];
    const float* in2 = (const float*)d_in[1];
    float* out = (float*)d_out;

    cudaFuncSetAttribute(corr3d_kernel,
                         cudaFuncAttributeMaxDynamicSharedMemorySize, SMEM_BYTES);

    dim3 grid(WW / TW, HH, BATCH * KD);   // 8 x 32 x 18 = 4608 blocks, z = dy*2 + b
    corr3d_kernel<<<grid, NTHR, SMEM_BYTES>>>(in1, in2, out);
}

// round 16
// speedup vs baseline: 1.6152x; 1.0292x over previous
#include <cuda_runtime.h>
#include <cstdint>
#include <cstddef>

typedef unsigned long long ull;

#define KD    9
#define PADV  4
#define BATCH 2
#define CCH   64
#define HH    32
#define WW    32
#define DD    32
#define TW    4
#define NTHR  288          // 9 dx * 4 wl * 8 dbk -> 9 warps, all active

#define CCHUNK 8
#define NCHUNK (CCH / CCHUNK)   // 8

// smem (floats):
//   in1 tile: [c][w][d]     stride 32 (no pad needed: per 8-lane LDS.128 phase,
//             granule = base + dbk -> all distinct -> conflict-free)
//   in2 halo: 2 buffers of [cc][row][d'] stride 40 (4 zero | 32 | 4 zero), 8-ch chunk
#define IN1_STRIDE 32
#define IN1_FLOATS (CCH*TW*IN1_STRIDE)              // 8192   (32768 B)
#define IN2_ROWS   12
#define IN2_STRIDE 40
#define IN2_BUF    (CCHUNK*IN2_ROWS*IN2_STRIDE)     // 3840   (15360 B)
#define IN2_FLOATS (2*IN2_BUF)                      // 7680
#define SMEM_BYTES ((IN1_FLOATS + IN2_FLOATS)*4)    // 63488 B -> 3 CTAs/SM

#define STAGE_V4 (CCHUNK*IN2_ROWS*8)                // 768 float4 per chunk
#define NLD 3                                       // ceil(768/288)

__device__ __forceinline__ ull pack2f(float lo, float hi) {
    ull r;
    asm("mov.b64 %0, {%1, %2};" : "=l"(r) : "f"(lo), "f"(hi));
    return r;
}
// packed f32x2 FMA: d = a*b + d  (FFMA2; only reachable via PTX)
__device__ __forceinline__ void ffma2(ull& d, ull a, ull b) {
    asm("fma.rn.f32x2 %0, %1, %2, %0;" : "+l"(d) : "l"(a), "l"(b));
}
__device__ __forceinline__ unsigned su32(const void* p) {
    return (unsigned)__cvta_generic_to_shared(p);
}
#define CP16(s, g)   asm volatile("cp.async.cg.shared.global [%0], [%1], 16;" :: "r"(s), "l"(g))
#define CP_COMMIT()  asm volatile("cp.async.commit_group;")
#define CP_WAIT0()   asm volatile("cp.async.wait_group 0;")

__global__ void __launch_bounds__(NTHR, 3)
corr3d_kernel(const float* __restrict__ in1, const float* __restrict__ in2,
              float* __restrict__ out)
{
    extern __shared__ float sm[];
    float* s1 = sm;               // in1 tile (all 64 channels)
    float* s2 = sm + IN1_FLOATS;  // in2 halo: two 8-channel buffers

    const int tid = threadIdx.x;
    const int w0  = blockIdx.x * TW;
    const int h   = blockIdx.y;
    const int b   = blockIdx.z & 1;        // z = dy*2 + b
    const int dy  = blockIdx.z >> 1;

    // thread mapping: tid = dx*32 + wl*8 + dbk  (warp == dx)
    const int dx  = tid >> 5;        // 0..8
    const int wl  = (tid >> 3) & 3;  // 0..3
    const int dbk = tid & 7;         // 0..7
    const int d0  = dbk << 2;        // 0,4,...,28
    const int row = wl + dx;         // in2 halo row index 0..11

    ull acc[KD][2];
    #pragma unroll
    for (int z = 0; z < KD; ++z) { acc[z][0] = 0ULL; acc[z][1] = 0ULL; }

    const int hp = h + dy - PADV;    // uniform across block
    if ((unsigned)hp < (unsigned)HH) {
        // Zero both in2 buffers (vectorized): d-edge pads and OOB-w rows stay
        // zero across restages (each chunk rewrites the same valid pattern).
        {
            float4 z4 = make_float4(0.f, 0.f, 0.f, 0.f);
            float4* z = reinterpret_cast<float4*>(s2);
            #pragma unroll 1
            for (int i = tid; i < IN2_FLOATS/4; i += NTHR) z[i] = z4;
        }

        // per-thread in2 staging geometry (chunk-invariant)
        const float* gdy = in2 + ((size_t)b*CCH)*HH*WW*DD + (size_t)hp*(WW*DD);
        unsigned st_sm[NLD];   // smem byte-offset within a buffer
        int      st_g[NLD];    // gmem float-offset from gdy (chunk channel 0)
        bool     st_ok[NLD];
        #pragma unroll
        for (int k = 0; k < NLD; ++k) {
            int i = tid + k*NTHR;
            if (i < STAGE_V4) {
                int j  = i & 7;
                int rr = i >> 3;            // 0..95
                int cl = rr / IN2_ROWS;     // 0..7
                int r  = rr - cl*IN2_ROWS;  // 0..11
                int wp = w0 + r - PADV;
                st_ok[k] = ((unsigned)wp < (unsigned)WW);
                st_sm[k] = (unsigned)(((cl*IN2_ROWS + r)*IN2_STRIDE + 4 + j*4) * 4);
                st_g[k]  = cl*(HH*WW*DD) + wp*DD + j*4;
            } else { st_ok[k] = false; st_sm[k] = 0; st_g[k] = 0; }
        }

        __syncthreads();   // zero-init drained before async copies land

        const unsigned sbase  = su32(s2);
        const unsigned s1base = su32(s1);

        // prologue group: full in1 tile + in2 chunk 0  (one commit)
        {
            const float* g1 = in1 + (((size_t)b*CCH)*HH + h)*(WW*DD);
            #pragma unroll 1
            for (int i = tid; i < CCH*TW*8; i += NTHR) {
                int j  = i & 7;
                int rw = i >> 3;
                int c  = rw >> 2;
                int w  = rw & 3;
                CP16(s1base + (unsigned)(((c*TW + w)*IN1_STRIDE + j*4)*4),
                     g1 + (size_t)c*(HH*WW*DD) + (w0 + w)*DD + j*4);
            }
            #pragma unroll
            for (int k = 0; k < NLD; ++k)
                if (st_ok[k]) CP16(sbase + st_sm[k], gdy + st_g[k]);
            CP_COMMIT();
        }

        for (int ck = 0; ck < NCHUNK; ++ck) {
            CP_WAIT0();        // chunk ck (and, at ck=0, the in1 tile) landed
            __syncthreads();   // data visible to all warps; compute(ck-1) finished

            // issue chunk ck+1 into the other buffer (last read by compute(ck-1))
            if (ck + 1 < NCHUNK) {
                const unsigned sb = sbase + (unsigned)(((ck + 1) & 1) * IN2_BUF * 4);
                const float* g = gdy + (size_t)((ck + 1)*CCHUNK)*(HH*WW*DD);
                #pragma unroll
                for (int k = 0; k < NLD; ++k)
                    if (st_ok[k]) CP16(sb + st_sm[k], g + st_g[k]);
                CP_COMMIT();
            }

            // compute chunk ck
            const ull* p1 = reinterpret_cast<const ull*>(s1)
                            + ((ck*CCHUNK)*TW + wl)*(IN1_STRIDE/2) + (d0 >> 1);
            const ull* p2 = reinterpret_cast<const ull*>(s2 + (ck & 1)*IN2_BUF)
                            + row*(IN2_STRIDE/2) + (d0 >> 1);
            #pragma unroll 1
            for (int c = 0; c < CCHUNK; ++c) {
                // V[0..5]: in2 floats [d0 .. d0+11]; A: in1 floats [d0..d0+3]
                ull V[6], A[2];
                {
                    ulonglong2 t0 = *reinterpret_cast<const ulonglong2*>(p2);
                    ulonglong2 t1 = *reinterpret_cast<const ulonglong2*>(p2 + 2);
                    ulonglong2 t2 = *reinterpret_cast<const ulonglong2*>(p2 + 4);
                    V[0]=t0.x; V[1]=t0.y; V[2]=t1.x; V[3]=t1.y; V[4]=t2.x; V[5]=t2.y;
                    ulonglong2 ta = *reinterpret_cast<const ulonglong2*>(p1);
                    A[0]=ta.x; A[1]=ta.y;
                }
                #pragma unroll
                for (int j = 0; j < 2; ++j) {
                    // even dz: aligned pairs straight from V
                    #pragma unroll
                    for (int dz = 0; dz < KD; dz += 2)
                        ffma2(acc[dz][j], V[j + (dz >> 1)], A[j]);
                    // odd dz: odd-aligned pair built on the fly
                    #pragma unroll
                    for (int dz = 1; dz < KD; dz += 2) {
                        int m = j + ((dz - 1) >> 1);
                        ull ov = pack2f(
                            __uint_as_float((unsigned)(V[m]   >> 32)),
                            __uint_as_float((unsigned)(V[m+1] & 0xFFFFFFFFu)));
                        ffma2(acc[dz][j], ov, A[j]);
                    }
                }
                p1 += TW * (IN1_STRIDE/2);        // 64 ull per channel
                p2 += IN2_ROWS * (IN2_STRIDE/2);  // 240 ull per channel
            }
        }
    }

    // write (zeros if hp was out of range — output buffer is poisoned)
    {
        const int kbase = (dy*KD + dx)*KD;
        float* op = out + (((size_t)b*(KD*KD*KD) + kbase)*HH + h)*(WW*DD)
                        + (w0 + wl)*DD + d0;
        #pragma unroll
        for (int dz = 0; dz < KD; ++dz) {
            ulonglong2 v0; v0.x = acc[dz][0]; v0.y = acc[dz][1];
            *reinterpret_cast<ulonglong2*>(op) = v0;     // 16B store, aligned
            op += (size_t)HH * WW * DD;                  // next dz channel
        }
    }
}

extern "C" void kernel_launch(void* const* d_in, const int* in_sizes, int n_in,
                              void* d_out, int out_size)
{
    const float* in1 = (const float*)d_in[0];
    const float* in2 = (const float*)d_in[1];
    float* out = (float*)d_out;

    cudaFuncSetAttribute(corr3d_kernel,
                         cudaFuncAttributeMaxDynamicSharedMemorySize, SMEM_BYTES);

    dim3 grid(WW / TW, HH, BATCH * KD);   // 8 x 32 x 18 = 4608 blocks, z = dy*2 + b
    corr3d_kernel<<<grid, NTHR, SMEM_BYTES>>>(in1, in2, out);
}

// round 17
// speedup vs baseline: 1.8346x; 1.1359x over previous
#include <cuda_runtime.h>
#include <cstdint>
#include <cstddef>

typedef unsigned long long ull;

#define KD    9
#define PADV  4
#define BATCH 2
#define CCH   64
#define HH    32
#define WW    32
#define DD    32
#define TW    4
#define NTHR  288          // 9 dx * 4 wl * 8 dbk -> 9 warps, all active

#define CCHUNK 8
#define NCHUNK (CCH / CCHUNK)   // 8

// smem (floats):
//   in1 tile: [c][w][d]     stride 32 (conflict-free for this lane map)
//   in2 halo: 2 buffers of [cc][row][d'] stride 40 (4 zero | 32 | 4 zero), 8-ch chunk
#define IN1_STRIDE 32
#define IN1_FLOATS (CCH*TW*IN1_STRIDE)              // 8192   (32768 B)
#define IN2_ROWS   12
#define IN2_STRIDE 40
#define IN2_BUF    (CCHUNK*IN2_ROWS*IN2_STRIDE)     // 3840   (15360 B)
#define IN2_FLOATS (2*IN2_BUF)                      // 7680
#define SMEM_BYTES ((IN1_FLOATS + IN2_FLOATS)*4)    // 63488 B -> 3 CTAs/SM

#define STAGE_V4 (CCHUNK*IN2_ROWS*8)                // 768 float4 per chunk
#define NLD 3                                       // ceil(768/288)

// packed f32x2 FMA: d = a*b + d  (FFMA2; only reachable via PTX)
__device__ __forceinline__ void ffma2(ull& d, ull a, ull b) {
    asm("fma.rn.f32x2 %0, %1, %2, %0;" : "+l"(d) : "l"(a), "l"(b));
}
// half-extracts: ptxas resolves these to direct use of the lo/hi register
__device__ __forceinline__ float lo32(ull v) { return __uint_as_float((unsigned)v); }
__device__ __forceinline__ float hi32(ull v) { return __uint_as_float((unsigned)(v >> 32)); }

__device__ __forceinline__ unsigned su32(const void* p) {
    return (unsigned)__cvta_generic_to_shared(p);
}
#define CP16(s, g)   asm volatile("cp.async.cg.shared.global [%0], [%1], 16;" :: "r"(s), "l"(g))
#define CP_COMMIT()  asm volatile("cp.async.commit_group;")
#define CP_WAIT0()   asm volatile("cp.async.wait_group 0;")

__global__ void __launch_bounds__(NTHR, 3)
corr3d_kernel(const float* __restrict__ in1, const float* __restrict__ in2,
              float* __restrict__ out)
{
    extern __shared__ float sm[];
    float* s1 = sm;               // in1 tile (all 64 channels)
    float* s2 = sm + IN1_FLOATS;  // in2 halo: two 8-channel buffers

    const int tid = threadIdx.x;
    const int w0  = blockIdx.x * TW;
    const int h   = blockIdx.y;
    const int b   = blockIdx.z & 1;        // z = dy*2 + b
    const int dy  = blockIdx.z >> 1;

    // thread mapping: tid = dx*32 + wl*8 + dbk  (warp == dx)
    const int dx  = tid >> 5;        // 0..8
    const int wl  = (tid >> 3) & 3;  // 0..3
    const int dbk = tid & 7;         // 0..7
    const int d0  = dbk << 2;        // 0,4,...,28
    const int row = wl + dx;         // in2 halo row index 0..11

    // even-dz accumulators as packed pairs, odd-dz as scalars
    ull   acc2[5][2];                // dz = 0,2,4,6,8
    float accf[4][4];                // dz = 1,3,5,7
    #pragma unroll
    for (int z = 0; z < 5; ++z) { acc2[z][0] = 0ULL; acc2[z][1] = 0ULL; }
    #pragma unroll
    for (int z = 0; z < 4; ++z)
        #pragma unroll
        for (int k = 0; k < 4; ++k) accf[z][k] = 0.0f;

    const int hp = h + dy - PADV;    // uniform across block
    if ((unsigned)hp < (unsigned)HH) {
        // Zero-init: only the d-pads of every row (valid cells are rewritten by
        // cp.async each chunk), plus full rows for OOB-w rows on edge blocks.
        {
            const float4 z4 = make_float4(0.f, 0.f, 0.f, 0.f);
            #pragma unroll 1
            for (int i = tid; i < 2*CCHUNK*IN2_ROWS; i += NTHR) {   // 192 rows
                float4* rp = reinterpret_cast<float4*>(s2 + i*IN2_STRIDE);
                rp[0] = z4;          // floats [0,4)
                rp[9] = z4;          // floats [36,40)
            }
            const int rlo = (w0 == 0) ? 0 : 8;
            if (w0 == 0 || w0 == (WW - TW)) {
                // 4 OOB rows per channel per buffer: zero their valid region too
                #pragma unroll 1
                for (int i = tid; i < 2*CCHUNK*4*8; i += NTHR) {    // 512 float4
                    int j  = i & 7;                 // 0..7 -> floats 4+4j
                    int rr = i >> 3;                // 0..63
                    int cb = rr >> 2;               // buffer*8 + cl combined: 0..15
                    int r  = rlo + (rr & 3);
                    reinterpret_cast<float4*>(
                        s2 + (cb*IN2_ROWS + r)*IN2_STRIDE + 4)[j] = z4;
                }
            }
        }

        // per-thread in2 staging geometry (chunk-invariant)
        const float* gdy = in2 + ((size_t)b*CCH)*HH*WW*DD + (size_t)hp*(WW*DD);
        unsigned st_sm[NLD];   // smem byte-offset within a buffer
        int      st_g[NLD];    // gmem float-offset from gdy (chunk channel 0)
        bool     st_ok[NLD];
        #pragma unroll
        for (int k = 0; k < NLD; ++k) {
            int i = tid + k*NTHR;
            if (i < STAGE_V4) {
                int j  = i & 7;
                int rr = i >> 3;            // 0..95
                int cl = rr / IN2_ROWS;     // 0..7
                int r  = rr - cl*IN2_ROWS;  // 0..11
                int wp = w0 + r - PADV;
                st_ok[k] = ((unsigned)wp < (unsigned)WW);
                st_sm[k] = (unsigned)(((cl*IN2_ROWS + r)*IN2_STRIDE + 4 + j*4) * 4);
                st_g[k]  = cl*(HH*WW*DD) + wp*DD + j*4;
            } else { st_ok[k] = false; st_sm[k] = 0; st_g[k] = 0; }
        }

        __syncthreads();   // zero-init drained before async copies land

        const unsigned sbase  = su32(s2);
        const unsigned s1base = su32(s1);

        // prologue group: full in1 tile + in2 chunk 0  (one commit)
        {
            const float* g1 = in1 + (((size_t)b*CCH)*HH + h)*(WW*DD);
            #pragma unroll 1
            for (int i = tid; i < CCH*TW*8; i += NTHR) {
                int j  = i & 7;
                int rw = i >> 3;
                int c  = rw >> 2;
                int w  = rw & 3;
                CP16(s1base + (unsigned)(((c*TW + w)*IN1_STRIDE + j*4)*4),
                     g1 + (size_t)c*(HH*WW*DD) + (w0 + w)*DD + j*4);
            }
            #pragma unroll
            for (int k = 0; k < NLD; ++k)
                if (st_ok[k]) CP16(sbase + st_sm[k], gdy + st_g[k]);
            CP_COMMIT();
        }

        for (int ck = 0; ck < NCHUNK; ++ck) {
            CP_WAIT0();        // chunk ck (and, at ck=0, the in1 tile) landed
            __syncthreads();   // data visible to all warps; compute(ck-1) finished

            // issue chunk ck+1 into the other buffer (last read by compute(ck-1))
            if (ck + 1 < NCHUNK) {
                const unsigned sb = sbase + (unsigned)(((ck + 1) & 1) * IN2_BUF * 4);
                const float* g = gdy + (size_t)((ck + 1)*CCHUNK)*(HH*WW*DD);
                #pragma unroll
                for (int k = 0; k < NLD; ++k)
                    if (st_ok[k]) CP16(sb + st_sm[k], g + st_g[k]);
                CP_COMMIT();
            }

            // compute chunk ck
            const ull* p1 = reinterpret_cast<const ull*>(s1)
                            + ((ck*CCHUNK)*TW + wl)*(IN1_STRIDE/2) + (d0 >> 1);
            const ull* p2 = reinterpret_cast<const ull*>(s2 + (ck & 1)*IN2_BUF)
                            + row*(IN2_STRIDE/2) + (d0 >> 1);
            #pragma unroll 1
            for (int c = 0; c < CCHUNK; ++c) {
                // V[0..5]: padded in2 floats [d0 .. d0+11]; A: in1 floats [d0..d0+3]
                ull V[6], A[2];
                {
                    ulonglong2 t0 = *reinterpret_cast<const ulonglong2*>(p2);
                    ulonglong2 t1 = *reinterpret_cast<const ulonglong2*>(p2 + 2);
                    ulonglong2 t2 = *reinterpret_cast<const ulonglong2*>(p2 + 4);
                    V[0]=t0.x; V[1]=t0.y; V[2]=t1.x; V[3]=t1.y; V[4]=t2.x; V[5]=t2.y;
                    ulonglong2 ta = *reinterpret_cast<const ulonglong2*>(p1);
                    A[0]=ta.x; A[1]=ta.y;
                }
                // even dz: aligned pairs -> packed FFMA2
                #pragma unroll
                for (int j = 0; j < 2; ++j) {
                    #pragma unroll
                    for (int dz = 0; dz < KD; dz += 2)
                        ffma2(acc2[dz >> 1][j], V[j + (dz >> 1)], A[j]);
                }
                // odd dz: scalar FFMA reading register halves directly (no repacks)
                #pragma unroll
                for (int dz = 1; dz < KD; dz += 2) {
                    const int o = (dz - 1) >> 1;
                    #pragma unroll
                    for (int j = 0; j < 2; ++j) {
                        const int m = j + o;            // (2j+dz)>>1
                        accf[o][2*j]   = fmaf(hi32(V[m]),   lo32(A[j]), accf[o][2*j]);
                        accf[o][2*j+1] = fmaf(lo32(V[m+1]), hi32(A[j]), accf[o][2*j+1]);
                    }
                }
                p1 += TW * (IN1_STRIDE/2);        // 64 ull per channel
                p2 += IN2_ROWS * (IN2_STRIDE/2);  // 240 ull per channel
            }
        }
    }

    // write (zeros if hp was out of range — output buffer is poisoned)
    {
        const int kbase = (dy*KD + dx)*KD;
        float* op = out + (((size_t)b*(KD*KD*KD) + kbase)*HH + h)*(WW*DD)
                        + (w0 + wl)*DD + d0;
        #pragma unroll
        for (int dz = 0; dz < KD; ++dz) {
            if ((dz & 1) == 0) {
                ulonglong2 v0; v0.x = acc2[dz >> 1][0]; v0.y = acc2[dz >> 1][1];
                *reinterpret_cast<ulonglong2*>(op) = v0;         // 16B store
            } else {
                const int o = (dz - 1) >> 1;
                *reinterpret_cast<float4*>(op) =
                    make_float4(accf[o][0], accf[o][1], accf[o][2], accf[o][3]);
            }
            op += (size_t)HH * WW * DD;   // next dz channel
        }
    }
}

extern "C" void kernel_launch(void* const* d_in, const int* in_sizes, int n_in,
                              void* d_out, int out_size)
{
    const float* in1 = (const float*)d_in[0];
    const float* in2 = (const float*)d_in[1];
    float* out = (float*)d_out;

    cudaFuncSetAttribute(corr3d_kernel,
                         cudaFuncAttributeMaxDynamicSharedMemorySize, SMEM_BYTES);

    dim3 grid(WW / TW, HH, BATCH * KD);   // 8 x 32 x 18 = 4608 blocks, z = dy*2 + b
    corr3d_kernel<<<grid, NTHR, SMEM_BYTES>>>(in1, in2, out);
}